// round 10
// baseline (speedup 1.0000x reference)
#include <cuda_runtime.h>
#include <cuda_fp16.h>
#include <cstdint>
#include <cstddef>

#define N_NODES 50000
#define N_ROWS_PAD 50048
#define N_EDGES 640000
#define N_REL   8
#define CH      128
#define KDIM    (N_REL * CH)                 // 1024
#define NBINS   (N_NODES * N_REL)
#define CAP     32

// Static device scratch (sanctioned no-cudaMalloc route)
__device__ int    g_cnt[NBINS];                      // per-(row,rel) edge count
__device__ int    g_bucket[(size_t)NBINS * CAP];     // block-transposed buckets
__device__ __half g_wh[KDIM * CH];                   // W fp16, [K=1024][128]
__device__ __half g_h[(size_t)N_ROWS_PAD * KDIM];    // H fp16, [rows][1024], 102.5MB

__device__ __forceinline__ size_t bucket_addr(int bin, int pos) {
    return (size_t)(bin >> 5) * (CAP * 32) + (size_t)pos * 32 + (bin & 31);
}

// ---------------------------------------------------------------------------
// helpers
// ---------------------------------------------------------------------------
__device__ __forceinline__ uint32_t smem_u32(const void* p) {
    uint32_t a;
    asm("{ .reg .u64 t; cvta.to.shared.u64 t, %1; cvt.u32.u64 %0, t; }" : "=r"(a) : "l"(p));
    return a;
}

__device__ __forceinline__ void ldsm_x4(uint32_t* r, uint32_t addr) {
    asm volatile("ldmatrix.sync.aligned.m8n8.x4.shared.b16 {%0,%1,%2,%3}, [%4];"
                 : "=r"(r[0]), "=r"(r[1]), "=r"(r[2]), "=r"(r[3]) : "r"(addr));
}

__device__ __forceinline__ void ldsm_x4_t(uint32_t* r, uint32_t addr) {
    asm volatile("ldmatrix.sync.aligned.m8n8.x4.trans.shared.b16 {%0,%1,%2,%3}, [%4];"
                 : "=r"(r[0]), "=r"(r[1]), "=r"(r[2]), "=r"(r[3]) : "r"(addr));
}

__device__ __forceinline__ void mma_f16(float* d, const uint32_t* a, const uint32_t* b) {
    asm volatile(
        "mma.sync.aligned.m16n8k16.row.col.f32.f16.f16.f32 "
        "{%0,%1,%2,%3}, {%4,%5,%6,%7}, {%8,%9}, {%0,%1,%2,%3};"
        : "+f"(d[0]), "+f"(d[1]), "+f"(d[2]), "+f"(d[3])
        : "r"(a[0]), "r"(a[1]), "r"(a[2]), "r"(a[3]), "r"(b[0]), "r"(b[1]));
}

// ---------------------------------------------------------------------------
// launch 0: zero the bucket counters
// ---------------------------------------------------------------------------
__global__ __launch_bounds__(256) void zero_cnt_kernel() {
    int i = blockIdx.x * 256 + threadIdx.x;
    if (i < NBINS) g_cnt[i] = 0;
}

// ---------------------------------------------------------------------------
// launch 1: convert W (fp32 [r][k][n] = [1024][128]) to fp16, same layout
// ---------------------------------------------------------------------------
__global__ __launch_bounds__(256) void prep_w_kernel(const float* __restrict__ w) {
    int i = blockIdx.x * 256 + threadIdx.x;
    if (i >= KDIM * CH / 4) return;
    float4 v = ((const float4*)w)[i];
    __half2 h0 = __floats2half2_rn(v.x, v.y);
    __half2 h1 = __floats2half2_rn(v.z, v.w);
    ((__half2*)g_wh)[i * 2]     = h0;
    ((__half2*)g_wh)[i * 2 + 1] = h1;
}

// ---------------------------------------------------------------------------
// launch 2: bucket edges by (dest row, relation), block-transposed layout.
// Bins are Poisson(mean 1.6); P(count > 32) ~ 1e-30.
// ---------------------------------------------------------------------------
__global__ __launch_bounds__(256) void scatter_kernel(const int* __restrict__ ei,
                                                      const int* __restrict__ et,
                                                      int E) {
    int e = blockIdx.x * 256 + threadIdx.x;
    if (e >= E) return;
    int row = ei[e];
    int col = ei[E + e];
    int t   = et[e];
    if ((unsigned)row >= N_NODES || (unsigned)col >= N_NODES || (unsigned)t >= N_REL)
        return;
    int bin = row * N_REL + t;
    int pos = atomicAdd(&g_cnt[bin], 1);
    if (pos < CAP) g_bucket[bucket_addr(bin, pos)] = col;
}

// ---------------------------------------------------------------------------
// launch 3: H build — one warp per node row, all 8 relations at once (MLP-8).
//   H[row][r*128+c] = sum_{e in bin(row,r)} x[col_e][c]   (fp32 acc -> fp16)
// Counted predicated loop: all 16 loads per iteration independent. No barriers.
// ---------------------------------------------------------------------------
__global__ __launch_bounds__(256) void h_kernel(const float* __restrict__ x) {
    int row  = (blockIdx.x * 256 + threadIdx.x) >> 5;
    int lane = threadIdx.x & 31;
    if (row >= N_NODES) return;

    const float4* x4 = (const float4*)x;
    const int binbase = row * N_REL;

    int cnt[N_REL];
    int m = 0;
    #pragma unroll
    for (int r = 0; r < N_REL; r++) {
        int cv = g_cnt[binbase + r];
        cnt[r] = (cv > CAP) ? CAP : cv;
        if (cnt[r] > m) m = cnt[r];
    }

    float4 acc[N_REL];
    #pragma unroll
    for (int r = 0; r < N_REL; r++) acc[r] = make_float4(0.f, 0.f, 0.f, 0.f);

    #pragma unroll 1
    for (int i = 0; i < m; i++) {
        int c[N_REL];
        #pragma unroll
        for (int r = 0; r < N_REL; r++)
            c[r] = (i < cnt[r]) ? g_bucket[bucket_addr(binbase + r, i)] : -1;
        float4 v[N_REL];
        #pragma unroll
        for (int r = 0; r < N_REL; r++)
            if (c[r] >= 0) v[r] = x4[(size_t)c[r] * 32 + lane];
        #pragma unroll
        for (int r = 0; r < N_REL; r++)
            if (c[r] >= 0) {
                acc[r].x += v[r].x; acc[r].y += v[r].y;
                acc[r].z += v[r].z; acc[r].w += v[r].w;
            }
    }

    __half* Hrow = g_h + (size_t)row * KDIM;
    #pragma unroll
    for (int r = 0; r < N_REL; r++) {
        __half2 h0 = __floats2half2_rn(acc[r].x, acc[r].y);
        __half2 h1 = __floats2half2_rn(acc[r].z, acc[r].w);
        uint2 u;
        u.x = *reinterpret_cast<uint32_t*>(&h0);
        u.y = *reinterpret_cast<uint32_t*>(&h1);
        *(uint2*)(Hrow + r * CH + lane * 4) = u;
    }
}

// ---------------------------------------------------------------------------
// launch 4: GEMM  out[50000,128] = H[50000,1024] @ Wflat[1024,128] + bias
// 512 threads (16 warps), CTA = 128 rows x 128 cols, K in 8 chunks of 128.
// Warp (wm=w&7, wn=w>>3): rows wm*16..+15, cols wn*64..+63, acc[8][4] held
// across chunks. Streamed As/Bs loads -> near-zero barrier imbalance.
// ---------------------------------------------------------------------------
#define PITCH_H  136
#define AS_BYTES (128 * PITCH_H * 2)
#define BS_BYTES (128 * PITCH_H * 2)
#define SMEM_GEMM (AS_BYTES + BS_BYTES)      // 69632

__global__ __launch_bounds__(512, 2) void gemm_kernel(const float* __restrict__ bias,
                                                      float* __restrict__ out) {
    extern __shared__ char smem[];
    char* AsB = smem;
    char* BsB = smem + AS_BYTES;

    const int tid  = threadIdx.x;
    const int warp = tid >> 5;
    const int lane = tid & 31;
    const int g    = lane >> 2;
    const int tig  = lane & 3;
    const int wm   = warp & 7;
    const int wn   = warp >> 3;
    const int row0 = blockIdx.x * 128;

    const uint32_t sAs = smem_u32(AsB);
    const uint32_t sBs = smem_u32(BsB);
    const uint32_t aAddr = sAs + (uint32_t)(wm * 16 + (lane & 15)) * 272u
                               + (uint32_t)(lane >> 4) * 16u;
    const uint32_t bAddr = sBs + (uint32_t)((lane & 7) + ((lane >> 3) & 1) * 8) * 272u
                               + (uint32_t)(lane >> 4) * 16u
                               + (uint32_t)wn * 128u;

    float acc[8][4];
    #pragma unroll
    for (int ni = 0; ni < 8; ni++)
        #pragma unroll
        for (int q = 0; q < 4; q++) acc[ni][q] = 0.f;

    #pragma unroll 1
    for (int kc = 0; kc < 8; kc++) {
        // As: 128 rows x 128 halves from g_h (2048 uint4, 4/thread, streamed)
        {
            #pragma unroll
            for (int it = 0; it < 4; it++) {
                int idx = it * 512 + tid;                 // 0..2047
                int rw  = idx >> 4;                       // row in tile
                int c16 = idx & 15;                       // uint4 within row
                uint4 v = *(const uint4*)(g_h + (size_t)(row0 + rw) * KDIM
                                              + kc * CH + c16 * 8);
                *(uint4*)(AsB + rw * 272 + c16 * 16) = v;
            }
        }
        // Bs: Wflat chunk [kc*128 .. +127][0..127] (2048 uint4, 4/thread)
        {
            const uint4* src = (const uint4*)(g_wh + (size_t)kc * CH * CH);
            #pragma unroll
            for (int it = 0; it < 4; it++) {
                int idx = it * 512 + tid;
                uint4 v = src[idx];
                *(uint4*)(BsB + (idx >> 4) * 272 + (idx & 15) * 16) = v;
            }
        }
        __syncthreads();

        #pragma unroll
        for (int ks = 0; ks < 8; ks++) {
            uint32_t af[4];
            ldsm_x4(af, aAddr + (uint32_t)ks * 32u);
            #pragma unroll
            for (int nip = 0; nip < 4; nip++) {
                uint32_t bf[4];
                ldsm_x4_t(bf, bAddr + (uint32_t)ks * 4352u + (uint32_t)nip * 32u);
                mma_f16(acc[nip * 2],     af, bf);
                mma_f16(acc[nip * 2 + 1], af, bf + 2);
            }
        }
        __syncthreads();
    }

    // ---- epilogue: out = acc + bias ----
    int r1 = row0 + wm * 16 + g;
    int r2 = r1 + 8;
    #pragma unroll
    for (int ni = 0; ni < 8; ni++) {
        int col = wn * 64 + ni * 8 + tig * 2;
        float b0 = bias[col], b1 = bias[col + 1];
        if (r1 < N_NODES) {
            float2 v = make_float2(acc[ni][0] + b0, acc[ni][1] + b1);
            *(float2*)(out + (size_t)r1 * CH + col) = v;
        }
        if (r2 < N_NODES) {
            float2 v = make_float2(acc[ni][2] + b0, acc[ni][3] + b1);
            *(float2*)(out + (size_t)r2 * CH + col) = v;
        }
    }
}

// ---------------------------------------------------------------------------
// kernel_launch
// inputs: x f32[50000*128], edge_index i32[2*640000], edge_type i32[640000],
//         weight f32[8*128*128], bias f32[128]
// ---------------------------------------------------------------------------
extern "C" void kernel_launch(void* const* d_in, const int* in_sizes, int n_in,
                              void* d_out, int out_size) {
    const float* x    = (const float*)d_in[0];
    const int*   ei   = (const int*)d_in[1];
    const int*   et   = (const int*)d_in[2];
    const float* w    = (const float*)d_in[3];
    const float* bias = (const float*)d_in[4];
    float* out = (float*)d_out;

    int E = in_sizes[2];
    if (E > N_EDGES) E = N_EDGES;

    cudaFuncSetAttribute(gemm_kernel, cudaFuncAttributeMaxDynamicSharedMemorySize,
                         SMEM_GEMM);

    zero_cnt_kernel<<<(NBINS + 255) / 256, 256>>>();                        // 0
    prep_w_kernel<<<(KDIM * CH / 4 + 255) / 256, 256>>>(w);                 // 1
    scatter_kernel<<<(E + 255) / 256, 256>>>(ei, et, E);                    // 2
    h_kernel<<<(N_NODES * 32 + 255) / 256, 256>>>(x);                       // 3
    gemm_kernel<<<(N_NODES + 127) / 128, 512, SMEM_GEMM>>>(bias, out);      // 4
}

// round 11
// speedup vs baseline: 1.8637x; 1.8637x over previous
#include <cuda_runtime.h>
#include <cuda_fp16.h>
#include <cstdint>
#include <cstddef>

#define N_NODES 50000
#define N_EDGES 640000
#define N_REL   8
#define CH      128
#define CAP     64

// Static device scratch (sanctioned no-cudaMalloc route)
__device__ int    g_cnt[N_NODES];                    // per-dest-row edge count
__device__ int    g_bucket[(size_t)N_NODES * CAP];   // keys: t*N_NODES+col (12.8MB)
__device__ __half g_wh[N_REL * CH * CH];             // W fp16 [r][k][n]
__device__ __half g_xt[(size_t)N_REL * N_NODES * CH];// xt fp16 [r][node][c], 102.4MB

// Block-transposed buckets: 32-bin blocks, each pos-level one 128B line.
__device__ __forceinline__ size_t bucket_addr(int bin, int pos) {
    return (size_t)(bin >> 5) * (CAP * 32) + (size_t)pos * 32 + (bin & 31);
}

// ---------------------------------------------------------------------------
// helpers
// ---------------------------------------------------------------------------
__device__ __forceinline__ uint32_t smem_u32(const void* p) {
    uint32_t a;
    asm("{ .reg .u64 t; cvta.to.shared.u64 t, %1; cvt.u32.u64 %0, t; }" : "=r"(a) : "l"(p));
    return a;
}

__device__ __forceinline__ void ldsm_x4(uint32_t* r, uint32_t addr) {
    asm volatile("ldmatrix.sync.aligned.m8n8.x4.shared.b16 {%0,%1,%2,%3}, [%4];"
                 : "=r"(r[0]), "=r"(r[1]), "=r"(r[2]), "=r"(r[3]) : "r"(addr));
}

__device__ __forceinline__ void ldsm_x4_t(uint32_t* r, uint32_t addr) {
    asm volatile("ldmatrix.sync.aligned.m8n8.x4.trans.shared.b16 {%0,%1,%2,%3}, [%4];"
                 : "=r"(r[0]), "=r"(r[1]), "=r"(r[2]), "=r"(r[3]) : "r"(addr));
}

__device__ __forceinline__ void mma_f16(float* d, const uint32_t* a, const uint32_t* b) {
    asm volatile(
        "mma.sync.aligned.m16n8k16.row.col.f32.f16.f16.f32 "
        "{%0,%1,%2,%3}, {%4,%5,%6,%7}, {%8,%9}, {%0,%1,%2,%3};"
        : "+f"(d[0]), "+f"(d[1]), "+f"(d[2]), "+f"(d[3])
        : "r"(a[0]), "r"(a[1]), "r"(a[2]), "r"(a[3]), "r"(b[0]), "r"(b[1]));
}

// ---------------------------------------------------------------------------
// launch 0: zero per-row counters
// ---------------------------------------------------------------------------
__global__ __launch_bounds__(256) void zero_cnt_kernel() {
    int i = blockIdx.x * 256 + threadIdx.x;
    if (i < N_NODES) g_cnt[i] = 0;
}

// ---------------------------------------------------------------------------
// launch 1: convert W to fp16, same [r][k][n] layout
// ---------------------------------------------------------------------------
__global__ __launch_bounds__(256) void prep_w_kernel(const float* __restrict__ w) {
    int i = blockIdx.x * 256 + threadIdx.x;
    if (i >= N_REL * CH * CH / 4) return;
    float4 v = ((const float4*)w)[i];
    __half2 h0 = __floats2half2_rn(v.x, v.y);
    __half2 h1 = __floats2half2_rn(v.z, v.w);
    ((__half2*)g_wh)[i * 2]     = h0;
    ((__half2*)g_wh)[i * 2 + 1] = h1;
}

// ---------------------------------------------------------------------------
// launch 2: bucket edges by dest row; key packs (rel, src col).
// Per-row counts are Poisson(12.8); P(count > 64) ~ 1e-40.
// ---------------------------------------------------------------------------
__global__ __launch_bounds__(256) void scatter_kernel(const int* __restrict__ ei,
                                                      const int* __restrict__ et,
                                                      int E) {
    int e = blockIdx.x * 256 + threadIdx.x;
    if (e >= E) return;
    int row = ei[e];
    int col = ei[E + e];
    int t   = et[e];
    if ((unsigned)row >= N_NODES || (unsigned)col >= N_NODES || (unsigned)t >= N_REL)
        return;
    int pos = atomicAdd(&g_cnt[row], 1);
    if (pos < CAP) g_bucket[bucket_addr(row, pos)] = t * N_NODES + col;
}

// ---------------------------------------------------------------------------
// launch 3: transform — xt[r] = x @ W[r], fp16 MMA, fp16 output.
// Grid (391, 8): CTA = 128 rows x 128 cols for one relation, K=128 one chunk.
// 512 threads (16 warps); warp (wm=w&7, wn=w>>3) -> rows wm*16..+15,
// cols wn*64..+63. x stays L2-resident across the 8 relation passes.
// ---------------------------------------------------------------------------
#define PITCH_H  136
#define AS_BYTES (128 * PITCH_H * 2)
#define BS_BYTES (128 * PITCH_H * 2)
#define SMEM_XT  (AS_BYTES + BS_BYTES)      // 69632

__global__ __launch_bounds__(512, 2) void xt_kernel(const float* __restrict__ x) {
    extern __shared__ char smem[];
    char* AsB = smem;
    char* BsB = smem + AS_BYTES;

    const int tid  = threadIdx.x;
    const int warp = tid >> 5;
    const int lane = tid & 31;
    const int g    = lane >> 2;
    const int tig  = lane & 3;
    const int wm   = warp & 7;
    const int wn   = warp >> 3;
    const int row0 = blockIdx.x * 128;
    const int rel  = blockIdx.y;

    const uint32_t sAs = smem_u32(AsB);
    const uint32_t sBs = smem_u32(BsB);
    const uint32_t aAddr = sAs + (uint32_t)(wm * 16 + (lane & 15)) * 272u
                               + (uint32_t)(lane >> 4) * 16u;
    const uint32_t bAddr = sBs + (uint32_t)((lane & 7) + ((lane >> 3) & 1) * 8) * 272u
                               + (uint32_t)(lane >> 4) * 16u
                               + (uint32_t)wn * 128u;

    // As: x rows row0..row0+127, fp32 -> fp16 (4096 float4, 8 per thread)
    #pragma unroll
    for (int it = 0; it < 8; it++) {
        int idx = it * 512 + tid;            // 0..4095
        int rw  = idx >> 5;                  // 32 float4 per row
        int c4  = idx & 31;
        int grow = row0 + rw;
        float4 v = make_float4(0.f, 0.f, 0.f, 0.f);
        if (grow < N_NODES)
            v = *(const float4*)(x + (size_t)grow * CH + c4 * 4);
        __half2 h0 = __floats2half2_rn(v.x, v.y);
        __half2 h1 = __floats2half2_rn(v.z, v.w);
        uint2 u;
        u.x = *reinterpret_cast<uint32_t*>(&h0);
        u.y = *reinterpret_cast<uint32_t*>(&h1);
        *(uint2*)(AsB + rw * 272 + c4 * 8) = u;
    }
    // Bs: W[rel] fp16 (2048 uint4, 4 per thread)
    {
        const uint4* src = (const uint4*)(g_wh + (size_t)rel * CH * CH);
        #pragma unroll
        for (int it = 0; it < 4; it++) {
            int idx = it * 512 + tid;
            uint4 v = src[idx];
            *(uint4*)(BsB + (idx >> 4) * 272 + (idx & 15) * 16) = v;
        }
    }
    __syncthreads();

    float acc[8][4];
    #pragma unroll
    for (int ni = 0; ni < 8; ni++)
        #pragma unroll
        for (int q = 0; q < 4; q++) acc[ni][q] = 0.f;

    #pragma unroll
    for (int ks = 0; ks < 8; ks++) {
        uint32_t af[4];
        ldsm_x4(af, aAddr + (uint32_t)ks * 32u);
        #pragma unroll
        for (int nip = 0; nip < 4; nip++) {
            uint32_t bf[4];
            ldsm_x4_t(bf, bAddr + (uint32_t)ks * 4352u + (uint32_t)nip * 32u);
            mma_f16(acc[nip * 2],     af, bf);
            mma_f16(acc[nip * 2 + 1], af, bf + 2);
        }
    }

    // epilogue: xt[rel][row][col] in fp16
    __half* outb = g_xt + (size_t)rel * N_NODES * CH;
    int r1 = row0 + wm * 16 + g;
    int r2 = r1 + 8;
    #pragma unroll
    for (int ni = 0; ni < 8; ni++) {
        int col = wn * 64 + ni * 8 + tig * 2;
        if (r1 < N_NODES) {
            __half2 h = __floats2half2_rn(acc[ni][0], acc[ni][1]);
            *(__half2*)(outb + (size_t)r1 * CH + col) = h;
        }
        if (r2 < N_NODES) {
            __half2 h = __floats2half2_rn(acc[ni][2], acc[ni][3]);
            *(__half2*)(outb + (size_t)r2 * CH + col) = h;
        }
    }
}

// ---------------------------------------------------------------------------
// launch 4: aggregate — warp per dest row, counted predicated loop (4-way
// unrolled, all loads independent -> deep MLP), no barriers, no atomics.
//   out[row][:] = bias + sum_i xt[key_i][:]    (fp16 gather, fp32 accumulate)
// ---------------------------------------------------------------------------
__global__ __launch_bounds__(256) void aggregate_kernel(const float* __restrict__ bias,
                                                        float* __restrict__ out) {
    int row  = (blockIdx.x * 256 + threadIdx.x) >> 5;
    int lane = threadIdx.x & 31;
    if (row >= N_NODES) return;

    int cnt = g_cnt[row];
    if (cnt > CAP) cnt = CAP;

    float4 acc = make_float4(0.f, 0.f, 0.f, 0.f);

    #pragma unroll 1
    for (int i = 0; i < cnt; i += 4) {
        int k[4];
        #pragma unroll
        for (int j = 0; j < 4; j++)
            k[j] = (i + j < cnt) ? g_bucket[bucket_addr(row, i + j)] : -1;
        uint2 u[4];
        #pragma unroll
        for (int j = 0; j < 4; j++)
            if (k[j] >= 0)
                u[j] = *(const uint2*)(g_xt + (size_t)k[j] * CH + lane * 4);
        #pragma unroll
        for (int j = 0; j < 4; j++)
            if (k[j] >= 0) {
                __half2 h0 = *reinterpret_cast<__half2*>(&u[j].x);
                __half2 h1 = *reinterpret_cast<__half2*>(&u[j].y);
                float2 f0 = __half22float2(h0);
                float2 f1 = __half22float2(h1);
                acc.x += f0.x; acc.y += f0.y; acc.z += f1.x; acc.w += f1.y;
            }
    }

    float4 b = ((const float4*)bias)[lane];
    float4 r;
    r.x = acc.x + b.x; r.y = acc.y + b.y;
    r.z = acc.z + b.z; r.w = acc.w + b.w;
    ((float4*)(out + (size_t)row * CH))[lane] = r;
}

// ---------------------------------------------------------------------------
// kernel_launch
// inputs: x f32[50000*128], edge_index i32[2*640000], edge_type i32[640000],
//         weight f32[8*128*128], bias f32[128]
// ---------------------------------------------------------------------------
extern "C" void kernel_launch(void* const* d_in, const int* in_sizes, int n_in,
                              void* d_out, int out_size) {
    const float* x    = (const float*)d_in[0];
    const int*   ei   = (const int*)d_in[1];
    const int*   et   = (const int*)d_in[2];
    const float* w    = (const float*)d_in[3];
    const float* bias = (const float*)d_in[4];
    float* out = (float*)d_out;

    int E = in_sizes[2];
    if (E > N_EDGES) E = N_EDGES;

    cudaFuncSetAttribute(xt_kernel, cudaFuncAttributeMaxDynamicSharedMemorySize,
                         SMEM_XT);

    zero_cnt_kernel<<<(N_NODES + 255) / 256, 256>>>();                      // 0
    prep_w_kernel<<<(N_REL * CH * CH / 4 + 255) / 256, 256>>>(w);           // 1
    scatter_kernel<<<(E + 255) / 256, 256>>>(ei, et, E);                    // 2
    dim3 tg((N_NODES + 127) / 128, N_REL);
    xt_kernel<<<tg, 512, SMEM_XT>>>(x);                                     // 3
    aggregate_kernel<<<(N_NODES * 32 + 255) / 256, 256>>>(bias, out);       // 4
}

// round 12
// speedup vs baseline: 1.8928x; 1.0156x over previous
#include <cuda_runtime.h>
#include <cuda_fp16.h>
#include <cstdint>
#include <cstddef>

#define N_NODES 50000
#define N_PAD   50048                        // pad to multiple of 128
#define N_EDGES 640000
#define N_REL   8
#define CH      128
#define CAP     64

// Static device scratch (sanctioned no-cudaMalloc route)
__device__ int    g_cnt[N_NODES];                    // per-dest-row edge count
__device__ int    g_bucket[(size_t)N_NODES * CAP];   // keys: t*N_NODES+col
__device__ __half g_wh[N_REL * CH * CH];             // W fp16 [r][k][n]
__device__ __half g_xh[(size_t)N_PAD * CH];          // x fp16 (12.8MB)
__device__ __half g_xt[(size_t)N_REL * N_NODES * CH];// xt fp16, 102.4MB

// Block-transposed buckets: 32-bin blocks, each pos-level one 128B line.
__device__ __forceinline__ size_t bucket_addr(int bin, int pos) {
    return (size_t)(bin >> 5) * (CAP * 32) + (size_t)pos * 32 + (bin & 31);
}

// ---------------------------------------------------------------------------
// helpers
// ---------------------------------------------------------------------------
__device__ __forceinline__ uint32_t smem_u32(const void* p) {
    uint32_t a;
    asm("{ .reg .u64 t; cvta.to.shared.u64 t, %1; cvt.u32.u64 %0, t; }" : "=r"(a) : "l"(p));
    return a;
}

__device__ __forceinline__ void ldsm_x4(uint32_t* r, uint32_t addr) {
    asm volatile("ldmatrix.sync.aligned.m8n8.x4.shared.b16 {%0,%1,%2,%3}, [%4];"
                 : "=r"(r[0]), "=r"(r[1]), "=r"(r[2]), "=r"(r[3]) : "r"(addr));
}

__device__ __forceinline__ void ldsm_x4_t(uint32_t* r, uint32_t addr) {
    asm volatile("ldmatrix.sync.aligned.m8n8.x4.trans.shared.b16 {%0,%1,%2,%3}, [%4];"
                 : "=r"(r[0]), "=r"(r[1]), "=r"(r[2]), "=r"(r[3]) : "r"(addr));
}

__device__ __forceinline__ void mma_f16(float* d, const uint32_t* a, const uint32_t* b) {
    asm volatile(
        "mma.sync.aligned.m16n8k16.row.col.f32.f16.f16.f32 "
        "{%0,%1,%2,%3}, {%4,%5,%6,%7}, {%8,%9}, {%0,%1,%2,%3};"
        : "+f"(d[0]), "+f"(d[1]), "+f"(d[2]), "+f"(d[3])
        : "r"(a[0]), "r"(a[1]), "r"(a[2]), "r"(a[3]), "r"(b[0]), "r"(b[1]));
}

// ---------------------------------------------------------------------------
// launch 0: zero per-row counters
// ---------------------------------------------------------------------------
__global__ __launch_bounds__(256) void zero_cnt_kernel() {
    int i = blockIdx.x * 256 + threadIdx.x;
    if (i < N_NODES) g_cnt[i] = 0;
}

// ---------------------------------------------------------------------------
// launch 1: W -> fp16 (same layout) ; also handles nothing else
// ---------------------------------------------------------------------------
__global__ __launch_bounds__(256) void prep_w_kernel(const float* __restrict__ w) {
    int i = blockIdx.x * 256 + threadIdx.x;
    if (i >= N_REL * CH * CH / 4) return;
    float4 v = ((const float4*)w)[i];
    __half2 h0 = __floats2half2_rn(v.x, v.y);
    __half2 h1 = __floats2half2_rn(v.z, v.w);
    ((__half2*)g_wh)[i * 2]     = h0;
    ((__half2*)g_wh)[i * 2 + 1] = h1;
}

// ---------------------------------------------------------------------------
// launch 2: x -> fp16 (rows >= N_NODES zero-padded)
// ---------------------------------------------------------------------------
__global__ __launch_bounds__(256) void prep_x_kernel(const float* __restrict__ x) {
    int i = blockIdx.x * 256 + threadIdx.x;          // float4 index
    if (i >= N_PAD * CH / 4) return;
    int row = i >> 5;
    float4 v = make_float4(0.f, 0.f, 0.f, 0.f);
    if (row < N_NODES) v = ((const float4*)x)[i];
    __half2 h0 = __floats2half2_rn(v.x, v.y);
    __half2 h1 = __floats2half2_rn(v.z, v.w);
    uint2 u;
    u.x = *reinterpret_cast<uint32_t*>(&h0);
    u.y = *reinterpret_cast<uint32_t*>(&h1);
    ((uint2*)g_xh)[i] = u;
}

// ---------------------------------------------------------------------------
// launch 3: bucket edges by dest row; key packs (rel, src col).
// Per-row counts Poisson(12.8); P(count > 64) ~ 1e-40.
// ---------------------------------------------------------------------------
__global__ __launch_bounds__(256) void scatter_kernel(const int* __restrict__ ei,
                                                      const int* __restrict__ et,
                                                      int E) {
    int e = blockIdx.x * 256 + threadIdx.x;
    if (e >= E) return;
    int row = ei[e];
    int col = ei[E + e];
    int t   = et[e];
    if ((unsigned)row >= N_NODES || (unsigned)col >= N_NODES || (unsigned)t >= N_REL)
        return;
    int pos = atomicAdd(&g_cnt[row], 1);
    if (pos < CAP) g_bucket[bucket_addr(row, pos)] = t * N_NODES + col;
}

// ---------------------------------------------------------------------------
// launch 4: transform — xt[r] = x @ W[r] for ALL r, one CTA per 128 rows.
// As (fp16 x tile) loaded ONCE; Bs swapped per relation. Warp = 32x32 tile
// (wm=warp&3 rows, wn=warp>>2 cols): LDSM 16KB/warp/rel (balanced A/B reuse).
// ---------------------------------------------------------------------------
#define PITCH_H  136
#define AS_BYTES (128 * PITCH_H * 2)
#define BS_BYTES (128 * PITCH_H * 2)
#define SMEM_XT  (AS_BYTES + BS_BYTES)      // 69632

__global__ __launch_bounds__(512, 2) void xt_kernel() {
    extern __shared__ char smem[];
    char* AsB = smem;
    char* BsB = smem + AS_BYTES;

    const int tid  = threadIdx.x;
    const int warp = tid >> 5;
    const int lane = tid & 31;
    const int g    = lane >> 2;
    const int tig  = lane & 3;
    const int wm   = warp & 3;               // 4 row-groups of 32
    const int wn   = warp >> 2;              // 4 col-groups of 32
    const int row0 = blockIdx.x * 128;

    const uint32_t sAs = smem_u32(AsB);
    const uint32_t sBs = smem_u32(BsB);
    const uint32_t aAddr = sAs + (uint32_t)(wm * 32 + (lane & 15)) * 272u
                               + (uint32_t)(lane >> 4) * 16u;
    const uint32_t bAddr = sBs + (uint32_t)((lane & 7) + ((lane >> 3) & 1) * 8) * 272u
                               + (uint32_t)(lane >> 4) * 16u
                               + (uint32_t)wn * 64u;

    // As: 128 rows x 128 halves from g_xh (2048 uint4, 4/thread) — ONCE
    #pragma unroll
    for (int it = 0; it < 4; it++) {
        int idx = it * 512 + tid;            // 0..2047
        int rw  = idx >> 4;
        int c16 = idx & 15;
        uint4 v = *(const uint4*)(g_xh + (size_t)(row0 + rw) * CH + c16 * 8);
        *(uint4*)(AsB + rw * 272 + c16 * 16) = v;
    }

    #pragma unroll 1
    for (int rel = 0; rel < N_REL; rel++) {
        // Bs: W[rel] fp16 (2048 uint4, 4/thread)
        {
            const uint4* src = (const uint4*)(g_wh + (size_t)rel * CH * CH);
            #pragma unroll
            for (int it = 0; it < 4; it++) {
                int idx = it * 512 + tid;
                uint4 v = src[idx];
                *(uint4*)(BsB + (idx >> 4) * 272 + (idx & 15) * 16) = v;
            }
        }
        __syncthreads();

        float acc[2][4][4];
        #pragma unroll
        for (int mi = 0; mi < 2; mi++)
            #pragma unroll
            for (int ni = 0; ni < 4; ni++)
                #pragma unroll
                for (int q = 0; q < 4; q++) acc[mi][ni][q] = 0.f;

        #pragma unroll
        for (int ks = 0; ks < 8; ks++) {
            uint32_t af[2][4];
            ldsm_x4(af[0], aAddr + (uint32_t)ks * 32u);
            ldsm_x4(af[1], aAddr + (uint32_t)ks * 32u + 16u * 272u);
            uint32_t bf[2][4];
            ldsm_x4_t(bf[0], bAddr + (uint32_t)ks * 4352u);
            ldsm_x4_t(bf[1], bAddr + (uint32_t)ks * 4352u + 32u);
            #pragma unroll
            for (int mi = 0; mi < 2; mi++)
                #pragma unroll
                for (int np = 0; np < 2; np++) {
                    mma_f16(acc[mi][np * 2],     af[mi], bf[np]);
                    mma_f16(acc[mi][np * 2 + 1], af[mi], bf[np] + 2);
                }
        }

        // epilogue: xt[rel] fp16
        __half* outb = g_xt + (size_t)rel * N_NODES * CH;
        #pragma unroll
        for (int mi = 0; mi < 2; mi++) {
            int r1 = row0 + wm * 32 + mi * 16 + g;
            int r2 = r1 + 8;
            #pragma unroll
            for (int ni = 0; ni < 4; ni++) {
                int col = wn * 32 + ni * 8 + tig * 2;
                if (r1 < N_NODES) {
                    __half2 h = __floats2half2_rn(acc[mi][ni][0], acc[mi][ni][1]);
                    *(__half2*)(outb + (size_t)r1 * CH + col) = h;
                }
                if (r2 < N_NODES) {
                    __half2 h = __floats2half2_rn(acc[mi][ni][2], acc[mi][ni][3]);
                    *(__half2*)(outb + (size_t)r2 * CH + col) = h;
                }
            }
        }
        __syncthreads();   // Bs consumed; safe to overwrite next relation
    }
}

// ---------------------------------------------------------------------------
// launch 5: aggregate — warp per dest row, counted predicated loop (4-way
// unrolled, independent loads -> deep MLP), no barriers, no atomics.
// ---------------------------------------------------------------------------
__global__ __launch_bounds__(256) void aggregate_kernel(const float* __restrict__ bias,
                                                        float* __restrict__ out) {
    int row  = (blockIdx.x * 256 + threadIdx.x) >> 5;
    int lane = threadIdx.x & 31;
    if (row >= N_NODES) return;

    int cnt = g_cnt[row];
    if (cnt > CAP) cnt = CAP;

    float4 acc = make_float4(0.f, 0.f, 0.f, 0.f);

    #pragma unroll 1
    for (int i = 0; i < cnt; i += 4) {
        int k[4];
        #pragma unroll
        for (int j = 0; j < 4; j++)
            k[j] = (i + j < cnt) ? g_bucket[bucket_addr(row, i + j)] : -1;
        uint2 u[4];
        #pragma unroll
        for (int j = 0; j < 4; j++)
            if (k[j] >= 0)
                u[j] = *(const uint2*)(g_xt + (size_t)k[j] * CH + lane * 4);
        #pragma unroll
        for (int j = 0; j < 4; j++)
            if (k[j] >= 0) {
                __half2 h0 = *reinterpret_cast<__half2*>(&u[j].x);
                __half2 h1 = *reinterpret_cast<__half2*>(&u[j].y);
                float2 f0 = __half22float2(h0);
                float2 f1 = __half22float2(h1);
                acc.x += f0.x; acc.y += f0.y; acc.z += f1.x; acc.w += f1.y;
            }
    }

    float4 b = ((const float4*)bias)[lane];
    float4 r;
    r.x = acc.x + b.x; r.y = acc.y + b.y;
    r.z = acc.z + b.z; r.w = acc.w + b.w;
    ((float4*)(out + (size_t)row * CH))[lane] = r;
}

// ---------------------------------------------------------------------------
// kernel_launch
// inputs: x f32[50000*128], edge_index i32[2*640000], edge_type i32[640000],
//         weight f32[8*128*128], bias f32[128]
// ---------------------------------------------------------------------------
extern "C" void kernel_launch(void* const* d_in, const int* in_sizes, int n_in,
                              void* d_out, int out_size) {
    const float* x    = (const float*)d_in[0];
    const int*   ei   = (const int*)d_in[1];
    const int*   et   = (const int*)d_in[2];
    const float* w    = (const float*)d_in[3];
    const float* bias = (const float*)d_in[4];
    float* out = (float*)d_out;

    int E = in_sizes[2];
    if (E > N_EDGES) E = N_EDGES;

    cudaFuncSetAttribute(xt_kernel, cudaFuncAttributeMaxDynamicSharedMemorySize,
                         SMEM_XT);

    zero_cnt_kernel<<<(N_NODES + 255) / 256, 256>>>();                      // 0
    prep_w_kernel<<<(N_REL * CH * CH / 4 + 255) / 256, 256>>>(w);           // 1
    prep_x_kernel<<<(N_PAD * CH / 4 + 255) / 256, 256>>>(x);                // 2
    scatter_kernel<<<(E + 255) / 256, 256>>>(ei, et, E);                    // 3
    xt_kernel<<<N_PAD / 128, 512, SMEM_XT>>>();                             // 4
    aggregate_kernel<<<(N_NODES * 32 + 255) / 256, 256>>>(bias, out);       // 5
}

// round 13
// speedup vs baseline: 1.9804x; 1.0463x over previous
#include <cuda_runtime.h>
#include <cuda_fp16.h>
#include <cstdint>
#include <cstddef>

#define N_NODES 50000
#define N_PAD   50048                        // pad to multiple of 128
#define N_EDGES 640000
#define N_REL   8
#define CH      128
#define CAP     64

// Static device scratch (sanctioned no-cudaMalloc route)
__device__ int    g_cnt[N_NODES];                    // per-dest-row edge count
__device__ int    g_bucket[(size_t)N_NODES * CAP];   // keys: t*N_NODES+col
__device__ __half g_wh[N_REL * CH * CH];             // W fp16 [r][k][n]
__device__ __half g_xh[(size_t)N_PAD * CH];          // x fp16 (12.8MB)
__device__ __half g_xt[(size_t)N_REL * N_NODES * CH];// xt fp16, 102.4MB

// Block-transposed buckets: 32-bin blocks, each pos-level one 128B line.
__device__ __forceinline__ size_t bucket_addr(int bin, int pos) {
    return (size_t)(bin >> 5) * (CAP * 32) + (size_t)pos * 32 + (bin & 31);
}

// ---------------------------------------------------------------------------
// helpers
// ---------------------------------------------------------------------------
__device__ __forceinline__ uint32_t smem_u32(const void* p) {
    uint32_t a;
    asm("{ .reg .u64 t; cvta.to.shared.u64 t, %1; cvt.u32.u64 %0, t; }" : "=r"(a) : "l"(p));
    return a;
}

__device__ __forceinline__ void ldsm_x4(uint32_t* r, uint32_t addr) {
    asm volatile("ldmatrix.sync.aligned.m8n8.x4.shared.b16 {%0,%1,%2,%3}, [%4];"
                 : "=r"(r[0]), "=r"(r[1]), "=r"(r[2]), "=r"(r[3]) : "r"(addr));
}

__device__ __forceinline__ void ldsm_x4_t(uint32_t* r, uint32_t addr) {
    asm volatile("ldmatrix.sync.aligned.m8n8.x4.trans.shared.b16 {%0,%1,%2,%3}, [%4];"
                 : "=r"(r[0]), "=r"(r[1]), "=r"(r[2]), "=r"(r[3]) : "r"(addr));
}

__device__ __forceinline__ void mma_f16(float* d, const uint32_t* a, const uint32_t* b) {
    asm volatile(
        "mma.sync.aligned.m16n8k16.row.col.f32.f16.f16.f32 "
        "{%0,%1,%2,%3}, {%4,%5,%6,%7}, {%8,%9}, {%0,%1,%2,%3};"
        : "+f"(d[0]), "+f"(d[1]), "+f"(d[2]), "+f"(d[3])
        : "r"(a[0]), "r"(a[1]), "r"(a[2]), "r"(a[3]), "r"(b[0]), "r"(b[1]));
}

// ---------------------------------------------------------------------------
// launch 0: zero per-row counters
// ---------------------------------------------------------------------------
__global__ __launch_bounds__(256) void zero_cnt_kernel() {
    int i = blockIdx.x * 256 + threadIdx.x;
    if (i < N_NODES) g_cnt[i] = 0;
}

// ---------------------------------------------------------------------------
// launch 1: W -> fp16 (same [r][k][n] layout)
// ---------------------------------------------------------------------------
__global__ __launch_bounds__(256) void prep_w_kernel(const float* __restrict__ w) {
    int i = blockIdx.x * 256 + threadIdx.x;
    if (i >= N_REL * CH * CH / 4) return;
    float4 v = ((const float4*)w)[i];
    __half2 h0 = __floats2half2_rn(v.x, v.y);
    __half2 h1 = __floats2half2_rn(v.z, v.w);
    ((__half2*)g_wh)[i * 2]     = h0;
    ((__half2*)g_wh)[i * 2 + 1] = h1;
}

// ---------------------------------------------------------------------------
// launch 2: x -> fp16 (rows >= N_NODES zero-padded)
// ---------------------------------------------------------------------------
__global__ __launch_bounds__(256) void prep_x_kernel(const float* __restrict__ x) {
    int i = blockIdx.x * 256 + threadIdx.x;          // float4 index
    if (i >= N_PAD * CH / 4) return;
    int row = i >> 5;
    float4 v = make_float4(0.f, 0.f, 0.f, 0.f);
    if (row < N_NODES) v = ((const float4*)x)[i];
    __half2 h0 = __floats2half2_rn(v.x, v.y);
    __half2 h1 = __floats2half2_rn(v.z, v.w);
    uint2 u;
    u.x = *reinterpret_cast<uint32_t*>(&h0);
    u.y = *reinterpret_cast<uint32_t*>(&h1);
    ((uint2*)g_xh)[i] = u;
}

// ---------------------------------------------------------------------------
// launch 3: bucket edges by dest row; key packs (rel, src col).
// Per-row counts Poisson(12.8); P(count > 64) ~ 1e-40.
// ---------------------------------------------------------------------------
__global__ __launch_bounds__(256) void scatter_kernel(const int* __restrict__ ei,
                                                      const int* __restrict__ et,
                                                      int E) {
    int e = blockIdx.x * 256 + threadIdx.x;
    if (e >= E) return;
    int row = ei[e];
    int col = ei[E + e];
    int t   = et[e];
    if ((unsigned)row >= N_NODES || (unsigned)col >= N_NODES || (unsigned)t >= N_REL)
        return;
    int pos = atomicAdd(&g_cnt[row], 1);
    if (pos < CAP) g_bucket[bucket_addr(row, pos)] = t * N_NODES + col;
}

// ---------------------------------------------------------------------------
// launch 4: transform — xt[r] = x @ W[r].
// Grid (391, 8): one-shot CTA per (128-row tile, relation) — deep wave
// overlap, a single __syncthreads. 256 threads (8 warps), warp tile 32x64
// (wm=warp&3 rows, wn=warp>>2 col-halves): LDSM 24KB/warp for 2048 outputs.
// ---------------------------------------------------------------------------
#define PITCH_H  136
#define AS_BYTES (128 * PITCH_H * 2)
#define BS_BYTES (128 * PITCH_H * 2)
#define SMEM_XT  (AS_BYTES + BS_BYTES)      // 69632

__global__ __launch_bounds__(256, 2) void xt_kernel() {
    extern __shared__ char smem[];
    char* AsB = smem;
    char* BsB = smem + AS_BYTES;

    const int tid  = threadIdx.x;
    const int warp = tid >> 5;
    const int lane = tid & 31;
    const int g    = lane >> 2;
    const int tig  = lane & 3;
    const int wm   = warp & 3;               // 4 row-groups of 32
    const int wn   = warp >> 2;              // 2 col-groups of 64
    const int row0 = blockIdx.x * 128;
    const int rel  = blockIdx.y;

    const uint32_t sAs = smem_u32(AsB);
    const uint32_t sBs = smem_u32(BsB);
    const uint32_t aAddr = sAs + (uint32_t)(wm * 32 + (lane & 15)) * 272u
                               + (uint32_t)(lane >> 4) * 16u;
    const uint32_t bAddr = sBs + (uint32_t)((lane & 7) + ((lane >> 3) & 1) * 8) * 272u
                               + (uint32_t)(lane >> 4) * 16u
                               + (uint32_t)wn * 128u;

    // As: 128x128 halves from g_xh (2048 uint4, 8/thread)
    #pragma unroll
    for (int it = 0; it < 8; it++) {
        int idx = it * 256 + tid;            // 0..2047
        int rw  = idx >> 4;
        int c16 = idx & 15;
        uint4 v = *(const uint4*)(g_xh + (size_t)(row0 + rw) * CH + c16 * 8);
        *(uint4*)(AsB + rw * 272 + c16 * 16) = v;
    }
    // Bs: W[rel] fp16 (2048 uint4, 8/thread)
    {
        const uint4* src = (const uint4*)(g_wh + (size_t)rel * CH * CH);
        #pragma unroll
        for (int it = 0; it < 8; it++) {
            int idx = it * 256 + tid;
            uint4 v = src[idx];
            *(uint4*)(BsB + (idx >> 4) * 272 + (idx & 15) * 16) = v;
        }
    }
    __syncthreads();

    float acc[2][8][4];
    #pragma unroll
    for (int mi = 0; mi < 2; mi++)
        #pragma unroll
        for (int ni = 0; ni < 8; ni++)
            #pragma unroll
            for (int q = 0; q < 4; q++) acc[mi][ni][q] = 0.f;

    #pragma unroll
    for (int ks = 0; ks < 8; ks++) {
        uint32_t af[2][4];
        ldsm_x4(af[0], aAddr + (uint32_t)ks * 32u);
        ldsm_x4(af[1], aAddr + (uint32_t)ks * 32u + 16u * 272u);
        uint32_t bf[4][4];
        #pragma unroll
        for (int p = 0; p < 4; p++)
            ldsm_x4_t(bf[p], bAddr + (uint32_t)ks * 4352u + (uint32_t)p * 32u);
        #pragma unroll
        for (int mi = 0; mi < 2; mi++)
            #pragma unroll
            for (int p = 0; p < 4; p++) {
                mma_f16(acc[mi][p * 2],     af[mi], bf[p]);
                mma_f16(acc[mi][p * 2 + 1], af[mi], bf[p] + 2);
            }
    }

    // epilogue: xt[rel] fp16
    __half* outb = g_xt + (size_t)rel * N_NODES * CH;
    #pragma unroll
    for (int mi = 0; mi < 2; mi++) {
        int r1 = row0 + wm * 32 + mi * 16 + g;
        int r2 = r1 + 8;
        #pragma unroll
        for (int ni = 0; ni < 8; ni++) {
            int col = wn * 64 + ni * 8 + tig * 2;
            if (r1 < N_NODES) {
                __half2 h = __floats2half2_rn(acc[mi][ni][0], acc[mi][ni][1]);
                *(__half2*)(outb + (size_t)r1 * CH + col) = h;
            }
            if (r2 < N_NODES) {
                __half2 h = __floats2half2_rn(acc[mi][ni][2], acc[mi][ni][3]);
                *(__half2*)(outb + (size_t)r2 * CH + col) = h;
            }
        }
    }
}

// ---------------------------------------------------------------------------
// launch 5: aggregate — warp per dest row, counted predicated loop (4-way
// unrolled, independent loads -> deep MLP), no barriers, no atomics.
// ---------------------------------------------------------------------------
__global__ __launch_bounds__(256) void aggregate_kernel(const float* __restrict__ bias,
                                                        float* __restrict__ out) {
    int row  = (blockIdx.x * 256 + threadIdx.x) >> 5;
    int lane = threadIdx.x & 31;
    if (row >= N_NODES) return;

    int cnt = g_cnt[row];
    if (cnt > CAP) cnt = CAP;

    float4 acc = make_float4(0.f, 0.f, 0.f, 0.f);

    #pragma unroll 1
    for (int i = 0; i < cnt; i += 4) {
        int k[4];
        #pragma unroll
        for (int j = 0; j < 4; j++)
            k[j] = (i + j < cnt) ? g_bucket[bucket_addr(row, i + j)] : -1;
        uint2 u[4];
        #pragma unroll
        for (int j = 0; j < 4; j++)
            if (k[j] >= 0)
                u[j] = *(const uint2*)(g_xt + (size_t)k[j] * CH + lane * 4);
        #pragma unroll
        for (int j = 0; j < 4; j++)
            if (k[j] >= 0) {
                __half2 h0 = *reinterpret_cast<__half2*>(&u[j].x);
                __half2 h1 = *reinterpret_cast<__half2*>(&u[j].y);
                float2 f0 = __half22float2(h0);
                float2 f1 = __half22float2(h1);
                acc.x += f0.x; acc.y += f0.y; acc.z += f1.x; acc.w += f1.y;
            }
    }

    float4 b = ((const float4*)bias)[lane];
    float4 r;
    r.x = acc.x + b.x; r.y = acc.y + b.y;
    r.z = acc.z + b.z; r.w = acc.w + b.w;
    ((float4*)(out + (size_t)row * CH))[lane] = r;
}

// ---------------------------------------------------------------------------
// kernel_launch
// inputs: x f32[50000*128], edge_index i32[2*640000], edge_type i32[640000],
//         weight f32[8*128*128], bias f32[128]
// ---------------------------------------------------------------------------
extern "C" void kernel_launch(void* const* d_in, const int* in_sizes, int n_in,
                              void* d_out, int out_size) {
    const float* x    = (const float*)d_in[0];
    const int*   ei   = (const int*)d_in[1];
    const int*   et   = (const int*)d_in[2];
    const float* w    = (const float*)d_in[3];
    const float* bias = (const float*)d_in[4];
    float* out = (float*)d_out;

    int E = in_sizes[2];
    if (E > N_EDGES) E = N_EDGES;

    cudaFuncSetAttribute(xt_kernel, cudaFuncAttributeMaxDynamicSharedMemorySize,
                         SMEM_XT);

    zero_cnt_kernel<<<(N_NODES + 255) / 256, 256>>>();                      // 0
    prep_w_kernel<<<(N_REL * CH * CH / 4 + 255) / 256, 256>>>(w);           // 1
    prep_x_kernel<<<(N_PAD * CH / 4 + 255) / 256, 256>>>(x);                // 2
    scatter_kernel<<<(E + 255) / 256, 256>>>(ei, et, E);                    // 3
    dim3 tg(N_PAD / 128, N_REL);
    xt_kernel<<<tg, 256, SMEM_XT>>>();                                      // 4
    aggregate_kernel<<<(N_NODES * 32 + 255) / 256, 256>>>(bias, out);       // 5
}